// round 5
// baseline (speedup 1.0000x reference)
#include <cuda_runtime.h>

// Dims fixed by reference setup_inputs()
static constexpr int Bn  = 16;
static constexpr int Tn  = 256;
static constexpr int Nn  = 2048;
static constexpr int CHn = 4;              // t-chunks per (b, n)
static constexpr int TCn = Tn / CHn;       // 64 frames per chunk
static constexpr int NPART = Bn * CHn;     // 64 partials per point
static constexpr int NPAIR = Nn / 2;       // 1024 point-pairs

static constexpr float LAMBDA_T = 0.5f;
static constexpr float LAMBDA_I = 0.1f;

// Moment scratch, layout [part][j][NPAIR] of float2 ({pt0, pt1}) — coalesced
// for both the k_main stores (lane = pair) and the k_id reads (lane = n).
// j: 0=count, 1..3=S1 pred, 4..6=S2 pred, 7..9=S1 gt, 10..12=S2 gt
__device__ float2 g_scr[NPART * 13 * NPAIR];
// Per-block partials from k_main: {recon, cvis, temp, cvel}
__device__ double g_part[512][4];
// Per-block identity partials from k_id
__device__ double g_idpart[64];

// ---------------------------------------------------------------------------
// Main fused pass: recon + temporal + per-point moments, single read of input.
// grid = 512 CTAs x 128 threads, 2 points/thread, one resident wave.
// ---------------------------------------------------------------------------
__global__ __launch_bounds__(128, 4) void k_main(const float* __restrict__ pred,
                                                 const float* __restrict__ gt,
                                                 const float* __restrict__ vis) {
    const int g    = blockIdx.x * 128 + threadIdx.x;
    const int pair = g & (NPAIR - 1);           // point pair id (fastest)
    const int part = g >> 10;                   // 0..63 = b*CH + chunk
    const int b    = part >> 2;
    const int chunk = part & 3;
    const int fr0  = b * Tn + chunk * TCn;

    const float2* __restrict__ p2 = (const float2*)pred;
    const float2* __restrict__ q2 = (const float2*)gt;
    const float2* __restrict__ v2 = (const float2*)vis;

    int vidx = fr0 * NPAIR + pair;              // float2 index into vis
    int ph   = vidx * 3;                        // float2 index into pred/gt

    float cnt[2] = {0.f, 0.f};
    float s1p[2][3] = {}, s2p[2][3] = {}, s1g[2][3] = {}, s2g[2][3] = {};
    float recon = 0.f, temp = 0.f, cvel = 0.f;

    float pp[2][3] = {}, pg[2][3] = {}, pm[2] = {0.f, 0.f};

    if (chunk != 0) {                           // seam frame t0-1
        float2 va = v2[vidx - NPAIR];
        pm[0] = va.x > 0.5f ? 1.f : 0.f;
        pm[1] = va.y > 0.5f ? 1.f : 0.f;
        float2 a = p2[ph - 3 * NPAIR], c = p2[ph - 3 * NPAIR + 1], d = p2[ph - 3 * NPAIR + 2];
        pp[0][0] = a.x; pp[0][1] = a.y; pp[0][2] = c.x;
        pp[1][0] = c.y; pp[1][1] = d.x; pp[1][2] = d.y;
        float2 e = q2[ph - 3 * NPAIR], f = q2[ph - 3 * NPAIR + 1], h = q2[ph - 3 * NPAIR + 2];
        pg[0][0] = e.x; pg[0][1] = e.y; pg[0][2] = f.x;
        pg[1][0] = f.y; pg[1][1] = h.x; pg[1][2] = h.y;
    }

    #pragma unroll 2
    for (int t = 0; t < TCn; ++t) {
        float2 va = v2[vidx];
        float2 a = p2[ph], c = p2[ph + 1], d = p2[ph + 2];
        float2 e = q2[ph], f = q2[ph + 1], h = q2[ph + 2];
        vidx += NPAIR; ph += 3 * NPAIR;

        float cm[2] = {va.x > 0.5f ? 1.f : 0.f, va.y > 0.5f ? 1.f : 0.f};
        float cp[2][3] = {{a.x, a.y, c.x}, {c.y, d.x, d.y}};
        float cg[2][3] = {{e.x, e.y, f.x}, {f.y, h.x, h.y}};

        #pragma unroll
        for (int k = 0; k < 2; ++k) {
            float m = cm[k];
            float d0 = cp[k][0] - cg[k][0];
            float d1 = cp[k][1] - cg[k][1];
            float d2 = cp[k][2] - cg[k][2];
            recon += m * (d0 * d0 + d1 * d1 + 2.f * d2 * d2);
            cnt[k] += m;

            float vm = m * pm[k];
            float v0 = (cp[k][0] - pp[k][0]) - (cg[k][0] - pg[k][0]);
            float v1 = (cp[k][1] - pp[k][1]) - (cg[k][1] - pg[k][1]);
            float v2c = (cp[k][2] - pp[k][2]) - (cg[k][2] - pg[k][2]);
            temp += vm * (v0 * v0 + v1 * v1 + v2c * v2c);
            cvel += vm;

            #pragma unroll
            for (int cc = 0; cc < 3; ++cc) {
                float mp = m * cp[k][cc];
                float mq = m * cg[k][cc];
                s1p[k][cc] += mp;  s2p[k][cc] += mp * cp[k][cc];
                s1g[k][cc] += mq;  s2g[k][cc] += mq * cg[k][cc];
                pp[k][cc] = cp[k][cc];
                pg[k][cc] = cg[k][cc];
            }
            pm[k] = m;
        }
    }

    // coalesced moment stores: [part][j][pair]
    float2* sc = g_scr + part * 13 * NPAIR + pair;
    sc[0 * NPAIR] = make_float2(cnt[0], cnt[1]);
    #pragma unroll
    for (int cc = 0; cc < 3; ++cc) {
        sc[(1 + cc)  * NPAIR] = make_float2(s1p[0][cc], s1p[1][cc]);
        sc[(4 + cc)  * NPAIR] = make_float2(s2p[0][cc], s2p[1][cc]);
        sc[(7 + cc)  * NPAIR] = make_float2(s1g[0][cc], s1g[1][cc]);
        sc[(10 + cc) * NPAIR] = make_float2(s2g[0][cc], s2g[1][cc]);
    }

    // block reduce (recon, cvis, temp, cvel) -> per-block doubles (no atomics)
    float cvis = cnt[0] + cnt[1];
    int lane = threadIdx.x & 31, w = threadIdx.x >> 5;
    #pragma unroll
    for (int o = 16; o; o >>= 1) {
        recon += __shfl_down_sync(0xffffffffu, recon, o);
        cvis  += __shfl_down_sync(0xffffffffu, cvis,  o);
        temp  += __shfl_down_sync(0xffffffffu, temp,  o);
        cvel  += __shfl_down_sync(0xffffffffu, cvel,  o);
    }
    __shared__ float sm4[4][4];
    if (lane == 0) { sm4[0][w] = recon; sm4[1][w] = cvis; sm4[2][w] = temp; sm4[3][w] = cvel; }
    __syncthreads();
    if (threadIdx.x == 0) {
        double r = 0, c = 0, tp = 0, cv = 0;
        #pragma unroll
        for (int i = 0; i < 4; ++i) {
            r += (double)sm4[0][i]; c += (double)sm4[1][i];
            tp += (double)sm4[2][i]; cv += (double)sm4[3][i];
        }
        g_part[blockIdx.x][0] = r;  g_part[blockIdx.x][1] = c;
        g_part[blockIdx.x][2] = tp; g_part[blockIdx.x][3] = cv;
    }
}

// ---------------------------------------------------------------------------
// Identity: 64 blocks x 416 threads. Warp j reduces moment j over 64 parts
// for 32 points (coalesced), shared exchange, warp0 computes variance ratios.
// ---------------------------------------------------------------------------
__global__ __launch_bounds__(416) void k_id() {
    const int nbase = blockIdx.x * 32;
    const int j = threadIdx.x >> 5;      // 0..12 (moment index)
    const int L = threadIdx.x & 31;      // point-within-group
    const int n = nbase + L;

    const float* __restrict__ sf = (const float*)g_scr;  // [part][j][Nn] floats
    double acc = 0.0;
    #pragma unroll 4
    for (int part = 0; part < NPART; ++part)
        acc += (double)sf[((part * 13 + j) << 11) + n];

    __shared__ double sm[13][33];
    sm[j][L] = acc;
    __syncthreads();

    if (j == 0) {
        double ratio = 0.0;
        double c0 = sm[0][L];
        if (c0 > 1.5) {                                 // n > 1
            double num = 0.0, den = 0.0;
            #pragma unroll
            for (int cc = 0; cc < 3; ++cc) {
                double s1pd = sm[1 + cc][L],  s2pd = sm[4 + cc][L];
                double s1gd = sm[7 + cc][L],  s2gd = sm[10 + cc][L];
                double pv = (s2pd - s1pd * (s1pd / c0)) / (c0 - 1.0);
                double gv = (s2gd - s1gd * (s1gd / c0)) / (c0 - 1.0);
                num += fabs(pv - gv);
                den += gv;
            }
            ratio = num / (den + 1e-6);
        }
        #pragma unroll
        for (int o = 16; o; o >>= 1)
            ratio += __shfl_down_sync(0xffffffffu, ratio, o);
        if (L == 0) g_idpart[blockIdx.x] = ratio;
    }
}

// ---------------------------------------------------------------------------
// Final: deterministic tree reduce of 512 block partials + 64 id partials,
// then adaptive re-weighting and the 4 outputs.
// ---------------------------------------------------------------------------
__global__ __launch_bounds__(128) void k_final(float* __restrict__ out) {
    __shared__ double s[128][4];
    __shared__ double sid[128];
    const int tid = threadIdx.x;

    double r = 0, c = 0, tp = 0, cv = 0;
    #pragma unroll
    for (int i = tid; i < 512; i += 128) {
        r  += g_part[i][0]; c  += g_part[i][1];
        tp += g_part[i][2]; cv += g_part[i][3];
    }
    s[tid][0] = r; s[tid][1] = c; s[tid][2] = tp; s[tid][3] = cv;
    sid[tid] = (tid < 64) ? g_idpart[tid] : 0.0;

    for (int o = 64; o; o >>= 1) {
        __syncthreads();
        if (tid < o) {
            #pragma unroll
            for (int k = 0; k < 4; ++k) s[tid][k] += s[tid + o][k];
            sid[tid] += sid[tid + o];
        }
    }
    __syncthreads();

    if (tid == 0) {
        double nvis = s[0][1], nvel = s[0][3];
        float recon    = (nvis > 0.0) ? (float)(s[0][0] / fmax(nvis, 1.0)) : 0.f;
        float temporal = (nvel > 0.0) ? (float)(s[0][2] / fmax(nvel, 1.0)) : 0.f;
        float identity = (float)(sid[0] / (double)Nn);

        float rl = recon, tl = temporal, il = identity;
        bool  all_pos = (rl > 0.f) && (tl > 0.f) && (il > 0.f);
        float maxc   = fmaxf(rl, fmaxf(tl, il));
        float target = maxc / 3.f;
        float thresh = 10.f * target;
        float rw = (all_pos && rl > thresh) ? 1.f      * target / fmaxf(rl, 1e-30f) : 1.f;
        float tw = (all_pos && tl > thresh) ? LAMBDA_T * target / fmaxf(tl, 1e-30f) : LAMBDA_T;
        float iw = (all_pos && il > thresh) ? LAMBDA_I * target / fmaxf(il, 1e-30f) : LAMBDA_I;

        out[0] = rw * rl + tw * tl + iw * il;
        out[1] = recon;
        out[2] = temporal;
        out[3] = identity;
    }
}

extern "C" void kernel_launch(void* const* d_in, const int* in_sizes, int n_in,
                              void* d_out, int out_size) {
    const float* pred = (const float*)d_in[0];
    const float* gt   = (const float*)d_in[1];
    const float* vis  = (const float*)d_in[2];
    float* out = (float*)d_out;

    k_main<<<512, 128>>>(pred, gt, vis);
    k_id<<<64, 416>>>();
    k_final<<<1, 128>>>(out);
}

// round 10
// speedup vs baseline: 1.1331x; 1.1331x over previous
#include <cuda_runtime.h>

// Dims fixed by reference setup_inputs()
static constexpr int Bn  = 16;
static constexpr int Tn  = 256;
static constexpr int Nn  = 2048;
static constexpr int CHn = 8;              // t-chunks per (b, n)
static constexpr int TCn = Tn / CHn;       // 32 frames per chunk
static constexpr int NPART = Bn * CHn;     // 128 partials per point
static constexpr int NPAIR = Nn / 2;       // 1024 point-pairs
static constexpr int NBLK  = (Bn * CHn * NPAIR) / 128;  // 1024 k_main blocks

static constexpr float LAMBDA_T = 0.5f;
static constexpr float LAMBDA_I = 0.1f;

// Moment scratch [part][j][NPAIR] float2 — coalesced for store and reload.
// j: 0=count, 1..3=S1 pred, 4..6=S2 pred, 7..9=S1 gt, 10..12=S2 gt
__device__ float2 g_scr[NPART * 13 * NPAIR];
// Per-block partials from k_main: {recon, cvis, temp, cvel}
__device__ double g_part[NBLK][4];
// Per-block identity partials, last-done counter
__device__ double g_idpart[64];
__device__ int    g_ctr;

// ---------------------------------------------------------------------------
// Fused pass: recon + temporal + per-point moments. 1024 CTAs x 128 thr,
// 2 points/thread, 7 blocks/SM (single wave, 28 warps/SM).
// ---------------------------------------------------------------------------
__global__ __launch_bounds__(128, 7) void k_main(const float* __restrict__ pred,
                                                 const float* __restrict__ gt,
                                                 const float* __restrict__ vis) {
    if (blockIdx.x == 0 && threadIdx.x == 0) g_ctr = 0;   // reset for k_id_final

    const int g     = blockIdx.x * 128 + threadIdx.x;
    const int pair  = g & (NPAIR - 1);
    const int part  = g >> 10;                  // 0..127 = b*CH + chunk
    const int b     = part >> 3;
    const int chunk = part & 7;
    const int fr0   = b * Tn + chunk * TCn;

    const float2* __restrict__ p2 = (const float2*)pred;
    const float2* __restrict__ q2 = (const float2*)gt;
    const float2* __restrict__ v2 = (const float2*)vis;

    int vidx = fr0 * NPAIR + pair;
    int ph   = vidx * 3;

    float cnt[2] = {0.f, 0.f};
    float s1p[2][3] = {}, s2p[2][3] = {}, s1g[2][3] = {}, s2g[2][3] = {};
    float recon = 0.f, temp = 0.f, cvel = 0.f;

    // prev-frame state: mask + (pred-gt) difference only
    float pm[2] = {0.f, 0.f};
    float pd[2][3] = {};

    if (chunk != 0) {                            // seam frame fr0-1
        float2 va = v2[vidx - NPAIR];
        pm[0] = va.x > 0.5f ? 1.f : 0.f;
        pm[1] = va.y > 0.5f ? 1.f : 0.f;
        float2 a = p2[ph - 3 * NPAIR], c = p2[ph - 3 * NPAIR + 1], d = p2[ph - 3 * NPAIR + 2];
        float2 e = q2[ph - 3 * NPAIR], f = q2[ph - 3 * NPAIR + 1], h = q2[ph - 3 * NPAIR + 2];
        pd[0][0] = a.x - e.x; pd[0][1] = a.y - e.y; pd[0][2] = c.x - f.x;
        pd[1][0] = c.y - f.y; pd[1][1] = d.x - h.x; pd[1][2] = d.y - h.y;
    }

    #pragma unroll 4
    for (int t = 0; t < TCn; ++t) {
        float2 va = v2[vidx];
        float2 a = p2[ph], c = p2[ph + 1], d = p2[ph + 2];
        float2 e = q2[ph], f = q2[ph + 1], h = q2[ph + 2];
        vidx += NPAIR; ph += 3 * NPAIR;

        float cm[2]    = {va.x > 0.5f ? 1.f : 0.f, va.y > 0.5f ? 1.f : 0.f};
        float cp[2][3] = {{a.x, a.y, c.x}, {c.y, d.x, d.y}};
        float cg[2][3] = {{e.x, e.y, f.x}, {f.y, h.x, h.y}};

        #pragma unroll
        for (int k = 0; k < 2; ++k) {
            float m  = cm[k];
            float d0 = cp[k][0] - cg[k][0];
            float d1 = cp[k][1] - cg[k][1];
            float d2 = cp[k][2] - cg[k][2];
            recon += m * (d0 * d0 + d1 * d1 + 2.f * d2 * d2);
            cnt[k] += m;

            float vm = m * pm[k];
            float v0 = d0 - pd[k][0];
            float v1 = d1 - pd[k][1];
            float v2c = d2 - pd[k][2];
            temp += vm * (v0 * v0 + v1 * v1 + v2c * v2c);
            cvel += vm;

            #pragma unroll
            for (int cc = 0; cc < 3; ++cc) {
                float mp = m * cp[k][cc];
                float mq = m * cg[k][cc];
                s1p[k][cc] += mp;  s2p[k][cc] += mp * cp[k][cc];
                s1g[k][cc] += mq;  s2g[k][cc] += mq * cg[k][cc];
            }
            pd[k][0] = d0; pd[k][1] = d1; pd[k][2] = d2;
            pm[k] = m;
        }
    }

    // coalesced moment stores
    float2* sc = g_scr + part * 13 * NPAIR + pair;
    sc[0 * NPAIR] = make_float2(cnt[0], cnt[1]);
    #pragma unroll
    for (int cc = 0; cc < 3; ++cc) {
        sc[(1 + cc)  * NPAIR] = make_float2(s1p[0][cc], s1p[1][cc]);
        sc[(4 + cc)  * NPAIR] = make_float2(s2p[0][cc], s2p[1][cc]);
        sc[(7 + cc)  * NPAIR] = make_float2(s1g[0][cc], s1g[1][cc]);
        sc[(10 + cc) * NPAIR] = make_float2(s2g[0][cc], s2g[1][cc]);
    }

    // block reduce (recon, cvis, temp, cvel) -> per-block doubles
    float cvis = cnt[0] + cnt[1];
    int lane = threadIdx.x & 31, w = threadIdx.x >> 5;
    #pragma unroll
    for (int o = 16; o; o >>= 1) {
        recon += __shfl_down_sync(0xffffffffu, recon, o);
        cvis  += __shfl_down_sync(0xffffffffu, cvis,  o);
        temp  += __shfl_down_sync(0xffffffffu, temp,  o);
        cvel  += __shfl_down_sync(0xffffffffu, cvel,  o);
    }
    __shared__ float sm4[4][4];
    if (lane == 0) { sm4[0][w] = recon; sm4[1][w] = cvis; sm4[2][w] = temp; sm4[3][w] = cvel; }
    __syncthreads();
    if (threadIdx.x == 0) {
        double r = 0, c = 0, tp = 0, cv = 0;
        #pragma unroll
        for (int i = 0; i < 4; ++i) {
            r += (double)sm4[0][i]; c += (double)sm4[1][i];
            tp += (double)sm4[2][i]; cv += (double)sm4[3][i];
        }
        g_part[blockIdx.x][0] = r;  g_part[blockIdx.x][1] = c;
        g_part[blockIdx.x][2] = tp; g_part[blockIdx.x][3] = cv;
    }
}

// ---------------------------------------------------------------------------
// Identity reduce + final combine (last-block-done). 64 blocks x 416 threads.
// ---------------------------------------------------------------------------
__global__ __launch_bounds__(416) void k_id_final(float* __restrict__ out) {
    const int tid = threadIdx.x;
    const int j = tid >> 5;              // moment index 0..12
    const int L = tid & 31;              // point within group
    const int n = blockIdx.x * 32 + L;

    const float* __restrict__ sf = (const float*)g_scr;  // [part][j][Nn]
    double acc = 0.0;
    #pragma unroll 8
    for (int part = 0; part < NPART; ++part)
        acc += (double)sf[((part * 13 + j) << 11) + n];

    __shared__ double sm[13][33];
    sm[j][L] = acc;
    __syncthreads();

    if (j == 0) {
        double ratio = 0.0;
        double c0 = sm[0][L];
        if (c0 > 1.5) {                  // n > 1 condition
            double num = 0.0, den = 0.0;
            #pragma unroll
            for (int cc = 0; cc < 3; ++cc) {
                double s1pd = sm[1 + cc][L], s2pd = sm[4 + cc][L];
                double s1gd = sm[7 + cc][L], s2gd = sm[10 + cc][L];
                double pv = (s2pd - s1pd * (s1pd / c0)) / (c0 - 1.0);
                double gv = (s2gd - s1gd * (s1gd / c0)) / (c0 - 1.0);
                num += fabs(pv - gv);
                den += gv;
            }
            ratio = num / (den + 1e-6);
        }
        #pragma unroll
        for (int o = 16; o; o >>= 1)
            ratio += __shfl_down_sync(0xffffffffu, ratio, o);
        if (L == 0) g_idpart[blockIdx.x] = ratio;   // tid == 0
    }

    // last-done election (writer is tid 0: write -> fence -> count)
    __shared__ int isLast;
    if (tid == 0) {
        __threadfence();
        isLast = (atomicAdd(&g_ctr, 1) == gridDim.x - 1);
    }
    __syncthreads();
    if (!isLast) return;
    __threadfence();

    // final combine: deterministic index-ordered sums
    double r = 0, c = 0, tp = 0, cv = 0, idv = 0;
    for (int i = tid; i < NBLK; i += 416) {
        r  += g_part[i][0]; c  += g_part[i][1];
        tp += g_part[i][2]; cv += g_part[i][3];
    }
    if (tid < 64) idv = g_idpart[tid];

    __shared__ double sr[13][5];
    #pragma unroll
    for (int o = 16; o; o >>= 1) {
        r   += __shfl_down_sync(0xffffffffu, r,   o);
        c   += __shfl_down_sync(0xffffffffu, c,   o);
        tp  += __shfl_down_sync(0xffffffffu, tp,  o);
        cv  += __shfl_down_sync(0xffffffffu, cv,  o);
        idv += __shfl_down_sync(0xffffffffu, idv, o);
    }
    if (L == 0) { sr[j][0] = r; sr[j][1] = c; sr[j][2] = tp; sr[j][3] = cv; sr[j][4] = idv; }
    __syncthreads();

    if (tid == 0) {
        double R = 0, C = 0, TP = 0, CV = 0, ID = 0;
        #pragma unroll
        for (int i = 0; i < 13; ++i) {
            R += sr[i][0]; C += sr[i][1]; TP += sr[i][2]; CV += sr[i][3]; ID += sr[i][4];
        }
        float recon    = (C  > 0.0) ? (float)(R  / fmax(C,  1.0)) : 0.f;
        float temporal = (CV > 0.0) ? (float)(TP / fmax(CV, 1.0)) : 0.f;
        float identity = (float)(ID / (double)Nn);

        float rl = recon, tl = temporal, il = identity;
        bool  all_pos = (rl > 0.f) && (tl > 0.f) && (il > 0.f);
        float target = fmaxf(rl, fmaxf(tl, il)) / 3.f;
        float thresh = 10.f * target;
        float rw = (all_pos && rl > thresh) ? 1.f      * target / fmaxf(rl, 1e-30f) : 1.f;
        float tw = (all_pos && tl > thresh) ? LAMBDA_T * target / fmaxf(tl, 1e-30f) : LAMBDA_T;
        float iw = (all_pos && il > thresh) ? LAMBDA_I * target / fmaxf(il, 1e-30f) : LAMBDA_I;

        out[0] = rw * rl + tw * tl + iw * il;
        out[1] = recon;
        out[2] = temporal;
        out[3] = identity;
    }
}

extern "C" void kernel_launch(void* const* d_in, const int* in_sizes, int n_in,
                              void* d_out, int out_size) {
    const float* pred = (const float*)d_in[0];
    const float* gt   = (const float*)d_in[1];
    const float* vis  = (const float*)d_in[2];
    float* out = (float*)d_out;

    k_main<<<NBLK, 128>>>(pred, gt, vis);
    k_id_final<<<64, 416>>>(out);
}